// round 10
// baseline (speedup 1.0000x reference)
#include <cuda_runtime.h>

typedef unsigned long long u64;

// ---- packed f32x2 helpers (sm_100+ PTX) ----
__device__ __forceinline__ u64 pk2(float a, float b) {
    u64 r; asm("mov.b64 %0,{%1,%2};" : "=l"(r) : "f"(a), "f"(b)); return r;
}
__device__ __forceinline__ void up2(u64 v, float& a, float& b) {
    asm("mov.b64 {%0,%1},%2;" : "=f"(a), "=f"(b) : "l"(v));
}
__device__ __forceinline__ u64 f2fma(u64 a, u64 b, u64 c) {
    u64 d; asm("fma.rn.f32x2 %0,%1,%2,%3;" : "=l"(d) : "l"(a), "l"(b), "l"(c)); return d;
}
__device__ __forceinline__ u64 f2mul(u64 a, u64 b) {
    u64 d; asm("mul.rn.f32x2 %0,%1,%2;" : "=l"(d) : "l"(a), "l"(b)); return d;
}
__host__ __device__ constexpr u64 PKC(float f) {
    unsigned u = __builtin_bit_cast(unsigned, f);
    return ((u64)u << 32) | (u64)u;
}

// Tsit5 coefficients
#define A21 0.161f
#define A31 (-0.008480655492356989f)
#define A32 0.335480655492357f
#define A41 2.8971530571054935f
#define A42 (-6.359448489975075f)
#define A43 4.3622954328695815f
#define A51 5.325864828439257f
#define A52 (-11.748883564062828f)
#define A53 7.4955393428898365f
#define A54 (-0.09249506636175525f)
#define A61 5.86145544294642f
#define A62 (-12.92096931784711f)
#define A63 8.159367898576159f
#define A64 (-0.071584973281401f)
#define A65 (-0.028269050394068383f)
#define B1 0.09646076681806523f
#define B2 0.01f
#define B3 0.4798896504144996f
#define B4 1.379008574103742f
#define B5 (-3.290069515436081f)
#define B6 2.324710524099774f
#define E1 (-0.001780011052225777f)
#define E2 (-0.0008164344596567469f)
#define E3 0.007880878010261995f
#define E4 (-0.1447110071732629f)
#define E5 0.5823571654525552f
#define E6 (-0.45808210592918697f)
#define E7 0.015151515151515152f

#define ATOL 1e-8f
#define RTOL 1e-4f
#define PRED_LEN 32
#define MAX_STEPS 12
#define FACC 1.0338287f   // 0.9 * 0.25^-0.1

// Packed RHS over two elements: kf = +inf = bN*S*I (S' = -inf handled by
// negated A/B constants in the S-chain), ki = inf - gm*I.
#define RHSP(S2v, I2v, kf, ki)                  \
    {                                           \
        u64 _si = f2mul((S2v), (I2v));          \
        kf = f2mul(bN2, _si);                   \
        ki = f2fma(ngm2, (I2v), kf);            \
    }

__global__ void __launch_bounds__(32) sird_kernel(
    const float* __restrict__ x,          // [B,3]
    const float* __restrict__ gp,         // [B,1]
    const float* __restrict__ population, // [B]
    float* __restrict__ out,              // [B,32,4]
    int B)
{
    const int half = B >> 1;
    const int tid = blockIdx.x * blockDim.x + threadIdx.x;
    if (tid >= half) return;
    const int ea = tid, eb = tid + half;

    const float beta_a = x[3 * ea + 0], gamma_a = x[3 * ea + 1], mu_a = x[3 * ea + 2];
    const float beta_b = x[3 * eb + 0], gamma_b = x[3 * eb + 1], mu_b = x[3 * eb + 2];
    const float bNa = beta_a / population[ea];
    const float bNb = beta_b / population[eb];
    const float gma = gamma_a + mu_a, gmb = gamma_b + mu_b;

    const u64 bN2  = pk2(bNa, bNb);
    const u64 ngm2 = pk2(-gma, -gmb);

    float Sa = gp[ea] - 100.0f, Ia = 100.0f, Ra = 0.0f, Da = 0.0f;
    float Sb = gp[eb] - 100.0f, Ib = 100.0f, Rb = 0.0f, Db = 0.0f;

    float4* rowa = reinterpret_cast<float4*>(out + (size_t)ea * (PRED_LEN * 4));
    float4* rowb = reinterpret_cast<float4*>(out + (size_t)eb * (PRED_LEN * 4));
    rowa[0] = make_float4(Sa, Ia, Ra, Da);
    rowb[0] = make_float4(Sb, Ib, Rb, Db);

    // FSAL carry: inf and kI at current state, per element
    float k1fa = bNa * Sa * Ia;
    float k1fb = bNb * Sb * Ib;
    float k1ia = fmaf(-gma, Ia, k1fa);
    float k1ib = fmaf(-gmb, Ib, k1fb);

    float dta = 0.05f, dtb = 0.05f;
    const float tstep = 32.0f / 31.0f;

    for (int iv = 0; iv < PRED_LEN - 1; ++iv) {
        const float t1 = (float)(iv + 1) * tstep;
        float ta = (float)iv * tstep, tb = ta;
        bool da = false, db = false;

        for (int s = 0; s < MAX_STEPS; ++s) {
            if (da && db) break;

            float ha = fmaxf(fminf(dta, t1 - ta), 1e-9f);
            float hb = fmaxf(fminf(dtb, t1 - tb), 1e-9f);
            u64 h2 = pk2(ha, hb);
            u64 S2 = pk2(Sa, Sb);
            u64 I2 = pk2(Ia, Ib);
            u64 k1f = pk2(k1fa, k1fb);
            u64 k1i = pk2(k1ia, k1ib);

            // stage 2
            u64 aS = f2fma(h2, f2mul(PKC(-A21), k1f), S2);
            u64 aI = f2fma(h2, f2mul(PKC(A21),  k1i), I2);
            const u64 I2s = aI;
            u64 k2f, k2i; RHSP(aS, aI, k2f, k2i);

            // stage 3
            aS = f2fma(h2, f2fma(PKC(-A32), k2f, f2mul(PKC(-A31), k1f)), S2);
            aI = f2fma(h2, f2fma(PKC(A32),  k2i, f2mul(PKC(A31),  k1i)), I2);
            const u64 I3s = aI;
            u64 k3f, k3i; RHSP(aS, aI, k3f, k3i);

            // stage 4
            aS = f2fma(h2, f2fma(PKC(-A43), k3f, f2fma(PKC(-A42), k2f, f2mul(PKC(-A41), k1f))), S2);
            aI = f2fma(h2, f2fma(PKC(A43),  k3i, f2fma(PKC(A42),  k2i, f2mul(PKC(A41),  k1i))), I2);
            const u64 I4s = aI;
            u64 k4f, k4i; RHSP(aS, aI, k4f, k4i);

            // stage 5
            aS = f2fma(h2, f2fma(PKC(-A54), k4f, f2fma(PKC(-A53), k3f, f2fma(PKC(-A52), k2f, f2mul(PKC(-A51), k1f)))), S2);
            aI = f2fma(h2, f2fma(PKC(A54),  k4i, f2fma(PKC(A53),  k3i, f2fma(PKC(A52),  k2i, f2mul(PKC(A51),  k1i)))), I2);
            const u64 I5s = aI;
            u64 k5f, k5i; RHSP(aS, aI, k5f, k5i);

            // stage 6
            aS = f2fma(h2, f2fma(PKC(-A65), k5f, f2fma(PKC(-A64), k4f, f2fma(PKC(-A63), k3f, f2fma(PKC(-A62), k2f, f2mul(PKC(-A61), k1f))))), S2);
            aI = f2fma(h2, f2fma(PKC(A65),  k5i, f2fma(PKC(A64),  k4i, f2fma(PKC(A63),  k3i, f2fma(PKC(A62),  k2i, f2mul(PKC(A61),  k1i))))), I2);
            const u64 I6s = aI;
            u64 k6f, k6i; RHSP(aS, aI, k6f, k6i);

            // y_new
            u64 nS2 = f2fma(h2,
                f2fma(PKC(-B6), k6f, f2fma(PKC(-B5), k5f, f2fma(PKC(-B4), k4f,
                    f2fma(PKC(-B3), k3f, f2fma(PKC(-B2), k2f, f2mul(PKC(-B1), k1f)))))), S2);
            u64 nI2 = f2fma(h2,
                f2fma(PKC(B6), k6i, f2fma(PKC(B5), k5i, f2fma(PKC(B4), k4i,
                    f2fma(PKC(B3), k3i, f2fma(PKC(B2), k2i, f2mul(PKC(B1), k1i)))))), I2);
            const u64 I7s = nI2;

            u64 k7f, k7i; RHSP(nS2, nI2, k7f, k7i);

            // error chains (sign of es irrelevant — only squared)
            u64 es2 = f2mul(h2,
                f2fma(PKC(E7), k7f, f2fma(PKC(E6), k6f, f2fma(PKC(E5), k5f,
                    f2fma(PKC(E4), k4f, f2fma(PKC(E3), k3f, f2fma(PKC(E2), k2f, f2mul(PKC(E1), k1f))))))));
            u64 ei2 = f2mul(h2,
                f2fma(PKC(E7), k7i, f2fma(PKC(E6), k6i, f2fma(PKC(E5), k5i,
                    f2fma(PKC(E4), k4i, f2fma(PKC(E3), k3i, f2fma(PKC(E2), k2i, f2mul(PKC(E1), k1i))))))));

            // I-stage sums for R/D (k_j^R = gamma*I_j, k_j^D = mu*I_j)
            u64 SB2 = f2fma(PKC(B6), I6s, f2fma(PKC(B5), I5s, f2fma(PKC(B4), I4s,
                        f2fma(PKC(B3), I3s, f2fma(PKC(B2), I2s, f2mul(PKC(B1), I2))))));
            u64 SE2 = f2fma(PKC(E7), I7s, f2fma(PKC(E6), I6s, f2fma(PKC(E5), I5s,
                        f2fma(PKC(E4), I4s, f2fma(PKC(E3), I3s, f2fma(PKC(E2), I2s, f2mul(PKC(E1), I2)))))));

            float nSa, nSb, nIa, nIb, esa, esb, eia, eib, SBa, SBb, SEa, SEb;
            float k7fa, k7fb, k7ia, k7ib;
            up2(nS2, nSa, nSb); up2(nI2, nIa, nIb);
            up2(es2, esa, esb); up2(ei2, eia, eib);
            up2(SB2, SBa, SBb); up2(SE2, SEa, SEb);
            up2(k7f, k7fa, k7fb); up2(k7i, k7ia, k7ib);

            // ---- controller, element a ----
            if (!da) {
                float hg = ha * gamma_a, hm = ha * mu_a;
                float nR = fmaf(hg, SBa, Ra);
                float nD = fmaf(hm, SBa, Da);
                float er = hg * SEa, ed = hm * SEa;
                float ts_ = fmaf(RTOL, fmaxf(fabsf(Sa), fabsf(nSa)), ATOL);
                float ti_ = fmaf(RTOL, fmaxf(fabsf(Ia), fabsf(nIa)), ATOL);
                float tr_ = fmaf(RTOL, fmaxf(fabsf(Ra), fabsf(nR)),  ATOL);
                float td_ = fmaf(RTOL, fmaxf(fabsf(Da), fabsf(nD)),  ATOL);
                float rs = __fdividef(esa, ts_), ri = __fdividef(eia, ti_);
                float rr = __fdividef(er,  tr_), rd = __fdividef(ed,  td_);
                float ss = fmaf(rs, rs, ri * ri) + fmaf(rr, rr, rd * rd);
                float fac = fminf(fmaxf(FACC * __powf(ss, -0.1f), 0.2f), 10.0f);
                dta = ha * fac;
                if (ss <= 4.0f) {
                    ta += ha;
                    Sa = nSa; Ia = nIa; Ra = nR; Da = nD;
                    k1fa = k7fa; k1ia = k7ia;
                }
                if (ta >= t1 - 1e-6f) da = true;
            }
            // ---- controller, element b ----
            if (!db) {
                float hg = hb * gamma_b, hm = hb * mu_b;
                float nR = fmaf(hg, SBb, Rb);
                float nD = fmaf(hm, SBb, Db);
                float er = hg * SEb, ed = hm * SEb;
                float ts_ = fmaf(RTOL, fmaxf(fabsf(Sb), fabsf(nSb)), ATOL);
                float ti_ = fmaf(RTOL, fmaxf(fabsf(Ib), fabsf(nIb)), ATOL);
                float tr_ = fmaf(RTOL, fmaxf(fabsf(Rb), fabsf(nR)),  ATOL);
                float td_ = fmaf(RTOL, fmaxf(fabsf(Db), fabsf(nD)),  ATOL);
                float rs = __fdividef(esb, ts_), ri = __fdividef(eib, ti_);
                float rr = __fdividef(er,  tr_), rd = __fdividef(ed,  td_);
                float ss = fmaf(rs, rs, ri * ri) + fmaf(rr, rr, rd * rd);
                float fac = fminf(fmaxf(FACC * __powf(ss, -0.1f), 0.2f), 10.0f);
                dtb = hb * fac;
                if (ss <= 4.0f) {
                    tb += hb;
                    Sb = nSb; Ib = nIb; Rb = nR; Db = nD;
                    k1fb = k7fb; k1ib = k7ib;
                }
                if (tb >= t1 - 1e-6f) db = true;
            }
        }

        rowa[iv + 1] = make_float4(Sa, Ia, Ra, Da);
        rowb[iv + 1] = make_float4(Sb, Ib, Rb, Db);
    }
}

extern "C" void kernel_launch(void* const* d_in, const int* in_sizes, int n_in,
                              void* d_out, int out_size)
{
    const float* x   = (const float*)d_in[0];
    const float* gp  = (const float*)d_in[1];
    const float* pop = (const float*)d_in[2];
    float* out = (float*)d_out;
    int B = in_sizes[2];

    int threads = 32;
    int nthreads_total = B / 2;
    int blocks = (nthreads_total + threads - 1) / threads;
    sird_kernel<<<blocks, threads>>>(x, gp, pop, out, B);
}

// round 11
// speedup vs baseline: 1.7332x; 1.7332x over previous
#include <cuda_runtime.h>

typedef unsigned long long u64;

// ---- packed f32x2 helpers (sm_100+ PTX) ----
__device__ __forceinline__ u64 pk2(float a, float b) {
    u64 r; asm("mov.b64 %0,{%1,%2};" : "=l"(r) : "f"(a), "f"(b)); return r;
}
__device__ __forceinline__ void up2(u64 v, float& a, float& b) {
    asm("mov.b64 {%0,%1},%2;" : "=f"(a), "=f"(b) : "l"(v));
}
__device__ __forceinline__ u64 f2fma(u64 a, u64 b, u64 c) {
    u64 d; asm("fma.rn.f32x2 %0,%1,%2,%3;" : "=l"(d) : "l"(a), "l"(b), "l"(c)); return d;
}
__device__ __forceinline__ u64 f2mul(u64 a, u64 b) {
    u64 d; asm("mul.rn.f32x2 %0,%1,%2;" : "=l"(d) : "l"(a), "l"(b)); return d;
}
__host__ __device__ constexpr u64 PKC(float f) {
    unsigned u = __builtin_bit_cast(unsigned, f);
    return ((u64)u << 32) | (u64)u;
}

// Tsit5 coefficients (fp32)
#define A21 0.161f
#define A31 (-0.008480655492356989f)
#define A32 0.335480655492357f
#define A41 2.8971530571054935f
#define A42 (-6.359448489975075f)
#define A43 4.3622954328695815f
#define A51 5.325864828439257f
#define A52 (-11.748883564062828f)
#define A53 7.4955393428898365f
#define A54 (-0.09249506636175525f)
#define A61 5.86145544294642f
#define A62 (-12.92096931784711f)
#define A63 8.159367898576159f
#define A64 (-0.071584973281401f)
#define A65 (-0.028269050394068383f)
#define B1 0.09646076681806523f
#define B2 0.01f
#define B3 0.4798896504144996f
#define B4 1.379008574103742f
#define B5 (-3.290069515436081f)
#define B6 2.324710524099774f
#define E1 (-0.001780011052225777f)
#define E2 (-0.0008164344596567469f)
#define E3 0.007880878010261995f
#define E4 (-0.1447110071732629f)
#define E5 0.5823571654525552f
#define E6 (-0.45808210592918697f)
#define E7 0.015151515151515152f

#define ATOL 1e-8f
#define RTOL 1e-4f
#define PRED_LEN 32
#define MAX_STEPS 12

// Integer-domain approximation of  FACC * ss^-0.1  (FACC = 0.9*0.25^-0.1):
//   bits(out) = C' - 0.1*bits(ss),  C' = 1.1*bits(1.0f) + log2(FACC)*2^23
// Error <= ~5% in fac — only perturbs step-size choice; accept test stays exact.
#define FAC_C 1172291263
#define FAC_TENTH 429496730u   // round(0.1 * 2^32)

// RHS producing packed k = (dS, dI). All negations folded into operand signs:
// infn = (-bN*S)*I = -inf; dS = infn; dI = inf - gm*I = fmaf(-gm, I, -infn).
#define PRHS(Sv, Iv, kout)                                 \
    {                                                      \
        float _m   = nbN * (Sv);                           \
        float _infn = _m * (Iv);                           \
        kout = pk2(_infn, fmaf(ngm, (Iv), -_infn));        \
    }

__global__ void __launch_bounds__(32) sird_kernel(
    const float* __restrict__ x,          // [B,3] beta,gamma,mu
    const float* __restrict__ gp,         // [B,1]
    const float* __restrict__ population, // [B]
    float* __restrict__ out,              // [B,32,4]
    int B)
{
    int b = blockIdx.x * blockDim.x + threadIdx.x;
    if (b >= B) return;

    const float beta  = x[3 * b + 0];
    const float gamma = x[3 * b + 1];
    const float mu    = x[3 * b + 2];
    const float N     = population[b];
    const float bN    = beta / N;
    const float nbN   = -bN;
    const float gm    = gamma + mu;
    const float ngm   = -gm;

    float S = gp[b] - 100.0f;
    float I = 100.0f;
    float R = 0.0f;
    float D = 0.0f;

    float4* orow = reinterpret_cast<float4*>(out + (size_t)b * (PRED_LEN * 4));
    orow[0] = make_float4(S, I, R, D);

    float dt = 0.05f;
    const float tstep = 32.0f / 31.0f;

    // FSAL: k1 = RHS(S, I) carried across steps (autonomous RHS; S,I change only
    // on accepted steps, where k1 := k7 = RHS(y_new)).
    u64 k1;
    PRHS(S, I, k1);

    for (int iv = 0; iv < PRED_LEN - 1; ++iv) {
        const float t1 = (float)(iv + 1) * tstep;
        float t = (float)iv * tstep;

        for (int s = 0; s < MAX_STEPS; ++s) {
            float h = fmaxf(fminf(dt, t1 - t), 1e-9f);
            u64 h2 = pk2(h, h);
            u64 y2 = pk2(S, I);

            float as, ai;
            const float I1 = I;

            u64 a2 = f2fma(h2, f2mul(PKC(A21), k1), y2);
            up2(a2, as, ai);
            const float I2 = ai;
            u64 k2; PRHS(as, ai, k2);

            a2 = f2fma(h2, f2fma(PKC(A32), k2, f2mul(PKC(A31), k1)), y2);
            up2(a2, as, ai);
            const float I3 = ai;
            u64 k3; PRHS(as, ai, k3);

            a2 = f2fma(h2, f2fma(PKC(A43), k3, f2fma(PKC(A42), k2, f2mul(PKC(A41), k1))), y2);
            up2(a2, as, ai);
            const float I4 = ai;
            u64 k4; PRHS(as, ai, k4);

            a2 = f2fma(h2, f2fma(PKC(A54), k4, f2fma(PKC(A53), k3, f2fma(PKC(A52), k2, f2mul(PKC(A51), k1)))), y2);
            up2(a2, as, ai);
            const float I5 = ai;
            u64 k5; PRHS(as, ai, k5);

            a2 = f2fma(h2, f2fma(PKC(A65), k5, f2fma(PKC(A64), k4, f2fma(PKC(A63), k3, f2fma(PKC(A62), k2, f2mul(PKC(A61), k1))))), y2);
            up2(a2, as, ai);
            const float I6 = ai;
            u64 k6; PRHS(as, ai, k6);

            u64 ny2 = f2fma(h2,
                f2fma(PKC(B6), k6, f2fma(PKC(B5), k5, f2fma(PKC(B4), k4,
                    f2fma(PKC(B3), k3, f2fma(PKC(B2), k2, f2mul(PKC(B1), k1)))))), y2);
            float nS, nI;
            up2(ny2, nS, nI);
            const float I7 = nI;

            // R/D via factored I-stage sums: k_j^R = gamma*I_j, k_j^D = mu*I_j
            const float SB = fmaf(B6, I6, fmaf(B5, I5, fmaf(B4, I4, fmaf(B3, I3, fmaf(B2, I2, B1 * I1)))));
            const float hg = h * gamma;
            const float hm = h * mu;
            float nR = fmaf(hg, SB, R);
            float nD = fmaf(hm, SB, D);

            u64 k7; PRHS(nS, nI, k7);

            // packed error estimate for (S, I)
            u64 e2 = f2mul(h2,
                f2fma(PKC(E7), k7, f2fma(PKC(E6), k6, f2fma(PKC(E5), k5,
                    f2fma(PKC(E4), k4, f2fma(PKC(E3), k3, f2fma(PKC(E2), k2, f2mul(PKC(E1), k1))))))));
            float es, ei;
            up2(e2, es, ei);

            const float SE = fmaf(E7, I7, fmaf(E6, I6, fmaf(E5, I5, fmaf(E4, I4, fmaf(E3, I3, fmaf(E2, I2, E1 * I1))))));
            float er = hg * SE;
            float ed = hm * SE;

            float ts_ = fmaf(RTOL, fmaxf(fabsf(S), fabsf(nS)), ATOL);
            float ti_ = fmaf(RTOL, fmaxf(fabsf(I), fabsf(nI)), ATOL);
            float tr_ = fmaf(RTOL, fmaxf(fabsf(R), fabsf(nR)), ATOL);
            float td_ = fmaf(RTOL, fmaxf(fabsf(D), fabsf(nD)), ATOL);

            float rs = __fdividef(es, ts_);
            float ri = __fdividef(ei, ti_);
            float rr = __fdividef(er, tr_);
            float rd = __fdividef(ed, td_);
            // ss = 4*enorm^2 ; accept test ss <= 4 equivalent to enorm <= 1
            float ss = fmaf(rs, rs, ri * ri) + fmaf(rr, rr, rd * rd);

            // fac ~= clip(FACC * ss^-0.1, 0.2, 10) via integer log-domain trick.
            // ss==0 -> yb = FAC_C -> huge -> clamp 10 (matches reference clip path).
            unsigned bs = (unsigned)__float_as_int(ss);
            int yb = FAC_C - (int)__umulhi(bs, FAC_TENTH);
            float fac = fminf(fmaxf(__int_as_float(yb), 0.2f), 10.0f);
            dt = h * fac;

            if (ss <= 4.0f) {
                t += h;
                S = nS; I = nI; R = nR; D = nD;
                k1 = k7;  // FSAL
            }
            if (t >= t1 - 1e-6f) break;
        }

        orow[iv + 1] = make_float4(S, I, R, D);
    }
}

extern "C" void kernel_launch(void* const* d_in, const int* in_sizes, int n_in,
                              void* d_out, int out_size)
{
    const float* x   = (const float*)d_in[0];
    const float* gp  = (const float*)d_in[1];
    const float* pop = (const float*)d_in[2];
    float* out = (float*)d_out;
    int B = in_sizes[2];  // population has B elements

    int threads = 32;
    int blocks = (B + threads - 1) / threads;
    sird_kernel<<<blocks, threads>>>(x, gp, pop, out, B);
}